// round 1
// baseline (speedup 1.0000x reference)
#include <cuda_runtime.h>
#include <cuda_bf16.h>
#include <cstdint>

// Fused adapter: out = x + 0.1f * ( relu( LN(x) @ Wd + bd ) @ Wu + bu )
// x: [32768, 768] fp32.  Wd: [768,16], Wu: [16,768].
//
// Design (see analysis): weights register-resident per thread, amortized over
// many rows per block (grid-stride). Packed f32x2 FMA for 2x fp32 MAC rate.
// Per row: block LN stats -> xn to smem -> warp-per-k-pair down dot ->
// per-thread up-proj from register weights -> residual add. Double-buffered
// x prefetch hides DRAM latency at occupancy 1 block/SM.

#define D_MODEL 768
#define NROWS   32768
#define NTHREADS 256
#define GRID    304   // 2 waves on 152 SMs at occupancy 1; keeps weight L2 refetch ~28 MB

typedef unsigned long long u64;

__device__ __forceinline__ u64 pk2(float x, float y) {
    u64 r; asm("mov.b64 %0,{%1,%2};" : "=l"(r) : "f"(x), "f"(y)); return r;
}
__device__ __forceinline__ void upk2(u64 v, float& x, float& y) {
    asm("mov.b64 {%0,%1},%2;" : "=f"(x), "=f"(y) : "l"(v));
}
// packed fp32x2 fma: r = a*b + c  (element-wise on both lanes)
__device__ __forceinline__ u64 ffma2(u64 a, u64 b, u64 c) {
    u64 r; asm("fma.rn.f32x2 %0,%1,%2,%3;" : "=l"(r) : "l"(a), "l"(b), "l"(c)); return r;
}

__global__ __launch_bounds__(NTHREADS)
void adapter_fused_kernel(const float* __restrict__ x,
                          const float* __restrict__ ln_g,
                          const float* __restrict__ ln_b,
                          const float* __restrict__ wd,   // [768][16]
                          const float* __restrict__ bd,   // [16]
                          const float* __restrict__ wu,   // [16][768]
                          const float* __restrict__ bu,   // [768]
                          float* __restrict__ out)
{
    __shared__ float  xn_s[D_MODEL];
    __shared__ float2 red_s[8];    // per-warp (sum, sumsq)
    __shared__ float2 down_s[8];   // 16 bottleneck activations as 8 float2

    const int t    = threadIdx.x;
    const int lane = t & 31;
    const int w    = t >> 5;       // warp id 0..7 -> k-pair (2w, 2w+1)

    // ---- preload weights into registers (once per block) ----
    // down-proj: lane owns d = 32*i + lane, i<24; holds (Wd[d][2w], Wd[d][2w+1])
    u64 wd2[24];
#pragma unroll
    for (int i = 0; i < 24; i++) {
        int d = i * 32 + lane;
        const float2 v = *reinterpret_cast<const float2*>(wd + d * 16 + 2 * w);
        wd2[i] = pk2(v.x, v.y);
    }
    const float2 bdw = *reinterpret_cast<const float2*>(bd + 2 * w);

    // up-proj: thread owns d_j = t + 256*j, j<3; holds (Wu[2p][d], Wu[2p+1][d]) p<8
    u64 wu2[3][8];
    float gj[3], bj[3], buj[3];
#pragma unroll
    for (int j = 0; j < 3; j++) {
        int d = t + 256 * j;
        gj[j]  = ln_g[d];
        bj[j]  = ln_b[d];
        buj[j] = bu[d];
#pragma unroll
        for (int p = 0; p < 8; p++)
            wu2[j][p] = pk2(wu[(2 * p) * D_MODEL + d], wu[(2 * p + 1) * D_MODEL + d]);
    }

    // ---- row loop (grid-stride), software-pipelined x load ----
    int row = blockIdx.x;
    float xc[3];
    if (row < NROWS) {
#pragma unroll
        for (int j = 0; j < 3; j++) xc[j] = x[row * D_MODEL + t + 256 * j];
    }

    while (row < NROWS) {
        const int nrow = row + gridDim.x;
        float xnx[3];
        if (nrow < NROWS) {
#pragma unroll
            for (int j = 0; j < 3; j++) xnx[j] = x[nrow * D_MODEL + t + 256 * j];
        }

        // ---- LN statistics ----
        float s = xc[0] + xc[1] + xc[2];
        float q = fmaf(xc[0], xc[0], fmaf(xc[1], xc[1], xc[2] * xc[2]));
#pragma unroll
        for (int o = 16; o; o >>= 1) {
            s += __shfl_xor_sync(0xFFFFFFFFu, s, o);
            q += __shfl_xor_sync(0xFFFFFFFFu, q, o);
        }
        if (lane == 0) red_s[w] = make_float2(s, q);
        __syncthreads();                               // b1
        float ts = 0.f, tq = 0.f;
#pragma unroll
        for (int i = 0; i < 8; i++) { float2 r = red_s[i]; ts += r.x; tq += r.y; }
        const float mean = ts * (1.0f / D_MODEL);
        const float var  = tq * (1.0f / D_MODEL) - mean * mean;
        const float rstd = rsqrtf(var + 1e-5f);

        // ---- normalize, stage xn in smem ----
#pragma unroll
        for (int j = 0; j < 3; j++) {
            float xn = (xc[j] - mean) * rstd * gj[j] + bj[j];
            xn_s[t + 256 * j] = xn;
        }
        __syncthreads();                               // b2

        // ---- down-proj: warp w computes bottleneck k = 2w, 2w+1 ----
        u64 acc[4] = {0ull, 0ull, 0ull, 0ull};
#pragma unroll
        for (int i = 0; i < 24; i++) {
            const float xs = xn_s[i * 32 + lane];
            acc[i & 3] = ffma2(pk2(xs, xs), wd2[i], acc[i & 3]);
        }
        float ax0, ay0, ax1, ay1, ax2, ay2, ax3, ay3;
        upk2(acc[0], ax0, ay0); upk2(acc[1], ax1, ay1);
        upk2(acc[2], ax2, ay2); upk2(acc[3], ax3, ay3);
        float ax = (ax0 + ax1) + (ax2 + ax3);
        float ay = (ay0 + ay1) + (ay2 + ay3);
#pragma unroll
        for (int o = 16; o; o >>= 1) {
            ax += __shfl_xor_sync(0xFFFFFFFFu, ax, o);
            ay += __shfl_xor_sync(0xFFFFFFFFu, ay, o);
        }
        if (lane == 0) {
            float d0 = fmaxf(ax + bdw.x, 0.0f);
            float d1 = fmaxf(ay + bdw.y, 0.0f);
            down_s[w] = make_float2(d0, d1);
        }
        __syncthreads();                               // b3

        // ---- up-proj + scale + residual ----
        u64 dn[8];
#pragma unroll
        for (int p = 0; p < 8; p++) { float2 dv = down_s[p]; dn[p] = pk2(dv.x, dv.y); }

#pragma unroll
        for (int j = 0; j < 3; j++) {
            u64 a0 = 0ull, a1 = 0ull;
#pragma unroll
            for (int p = 0; p < 8; p += 2) {
                a0 = ffma2(dn[p],     wu2[j][p],     a0);
                a1 = ffma2(dn[p + 1], wu2[j][p + 1], a1);
            }
            float sx0, sy0, sx1, sy1;
            upk2(a0, sx0, sy0); upk2(a1, sx1, sy1);
            const float up = (sx0 + sy0) + (sx1 + sy1);
            out[row * D_MODEL + t + 256 * j] = fmaf(0.1f, up + buj[j], xc[j]);
        }

        // advance (no barrier needed: next writes to red_s/xn_s are gated
        // behind b1/b2 of the next iteration, which dominate b3 of this one)
        row = nrow;
#pragma unroll
        for (int j = 0; j < 3; j++) xc[j] = xnx[j];
    }
}

extern "C" void kernel_launch(void* const* d_in, const int* in_sizes, int n_in,
                              void* d_out, int out_size)
{
    const float* x    = (const float*)d_in[0];
    const float* ln_g = (const float*)d_in[1];
    const float* ln_b = (const float*)d_in[2];
    const float* wd   = (const float*)d_in[3];
    const float* bd   = (const float*)d_in[4];
    const float* wu   = (const float*)d_in[5];
    const float* bu   = (const float*)d_in[6];
    float* out = (float*)d_out;

    adapter_fused_kernel<<<GRID, NTHREADS>>>(x, ln_g, ln_b, wd, bd, wu, bu, out);
}

// round 4
// speedup vs baseline: 2.1042x; 2.1042x over previous
#include <cuda_runtime.h>
#include <cuda_bf16.h>
#include <cstdint>

// Fused adapter: out = x + 0.1f * ( relu( LN(x) @ Wd + bd ) @ Wu + bu )
// x: [32768, 768] fp32.  Wd: [768,16], Wu: [16,768].
//
// R4: R3 structure (8-row batches, persistent blocks, register weights,
// f32x2 packed FMA) with CONVERGENT keep/send butterfly reductions:
// every __shfl_xor_sync is unconditional, values are selected before the
// shuffle. 9 SHFL reduce 8 values warp-wide; 1 SHFL stage for the LN pair.

#define D_MODEL  768
#define NROWS    32768
#define NTHREADS 256
#define RB       8              // rows per batch
#define GRID     152            // persistent: one block per SM
#define NBATCH   (NROWS / RB)   // 4096

typedef unsigned long long u64;

__device__ __forceinline__ u64 pk2(float x, float y) {
    u64 r; asm("mov.b64 %0,{%1,%2};" : "=l"(r) : "f"(x), "f"(y)); return r;
}
__device__ __forceinline__ void upk2(u64 v, float& x, float& y) {
    asm("mov.b64 {%0,%1},%2;" : "=f"(x), "=f"(y) : "l"(v));
}
__device__ __forceinline__ u64 ffma2(u64 a, u64 b, u64 c) {
    u64 r; asm("fma.rn.f32x2 %0,%1,%2,%3;" : "=l"(r) : "l"(a), "l"(b), "l"(c)); return r;
}
__device__ __forceinline__ float shx(float v, int off) {
    return __shfl_xor_sync(0xFFFFFFFFu, v, off);
}
// Convergent pair-combine: lane keeps `a` if !hi else `b`, receives the
// partner's complementary value via ONE unconditional shuffle.
__device__ __forceinline__ float bfly(float a, float b, bool hi, int off) {
    const float keep = hi ? b : a;
    const float send = hi ? a : b;
    return keep + shx(send, off);
}

__global__ __launch_bounds__(NTHREADS, 1)
void adapter_fused_kernel(const float* __restrict__ x,
                          const float* __restrict__ ln_g,
                          const float* __restrict__ ln_b,
                          const float* __restrict__ wd,   // [768][16]
                          const float* __restrict__ bd,   // [16]
                          const float* __restrict__ wu,   // [16][768]
                          const float* __restrict__ bu,   // [768]
                          float* __restrict__ out)
{
    __shared__ __align__(16) float  xn_s[RB * D_MODEL];   // 24 KB
    __shared__ __align__(16) float  red_s[RB * 16];       // per (row, warp): s,q
    __shared__ __align__(16) float2 stats_s[RB];          // per row (mean, rstd)
    __shared__ __align__(16) float  dpart[RB * 16 * 4];   // row: 16 k x 4 d-groups
    __shared__ __align__(16) float  down_f[RB * 16];      // row: 16 relu'd acts
    __shared__ __align__(16) float  bd_s[16];

    const int t    = threadIdx.x;
    const int lane = t & 31;
    const int w    = t >> 5;       // warp 0..7
    const int c    = w & 1;        // k-chunk: k in [8c, 8c+8)
    const int g    = w >> 1;       // d-group: d in [192g, 192g+192)

    if (t < 16) bd_s[t] = bd[t];

    // ---- register-resident weights (once per block) ----
    u64 wd2[6][4];
#pragma unroll
    for (int i = 0; i < 6; i++) {
        const int d = 192 * g + 32 * i + lane;
#pragma unroll
        for (int p = 0; p < 4; p++) {
            const float2 v = *reinterpret_cast<const float2*>(wd + d * 16 + 8 * c + 2 * p);
            wd2[i][p] = pk2(v.x, v.y);
        }
    }
    u64 wu2[3][8];
    float gj[3], bj[3], buj[3];
#pragma unroll
    for (int j = 0; j < 3; j++) {
        const int d = t + 256 * j;
        gj[j]  = ln_g[d];
        bj[j]  = ln_b[d];
        buj[j] = bu[d];
#pragma unroll
        for (int p = 0; p < 8; p++)
            wu2[j][p] = pk2(wu[(2 * p) * D_MODEL + d], wu[(2 * p + 1) * D_MODEL + d]);
    }

    const bool hi16 = (lane & 16) != 0;
    const bool hi8  = (lane & 8)  != 0;
    const bool hi4  = (lane & 4)  != 0;

    // ---- batch loop (persistent, grid-stride over 8-row batches) ----
    int b = blockIdx.x;
    float xc[RB][3];
    {
        const int rbase = b * RB;
#pragma unroll
        for (int r = 0; r < RB; r++)
#pragma unroll
            for (int j = 0; j < 3; j++)
                xc[r][j] = x[(rbase + r) * D_MODEL + t + 256 * j];
    }

    while (b < NBATCH) {
        const int rbase = b * RB;
        const int nb    = b + GRID;

        // -- LN partial stats: keep/send split (1 SHFL) + 4-SHFL tree --
#pragma unroll
        for (int r = 0; r < RB; r++) {
            float s = (xc[r][0] + xc[r][1]) + xc[r][2];
            float q = fmaf(xc[r][0], xc[r][0], fmaf(xc[r][1], xc[r][1], xc[r][2] * xc[r][2]));
            float m = bfly(s, q, hi16, 16);   // lanes 0-15 carry s, 16-31 carry q
            m += shx(m, 8); m += shx(m, 4); m += shx(m, 2); m += shx(m, 1);
            if ((lane & 15) == 0)
                red_s[r * 16 + 2 * w + (lane >> 4)] = m;   // [s, q] per warp
        }
        __syncthreads();                                    // b1

        // -- finalize stats: warp w handles row w (8 partial pairs) --
        {
            const float2 rr = reinterpret_cast<const float2*>(red_s)[w * 8 + (lane & 7)];
            float s = rr.x, q = rr.y;
            s += shx(s, 4); q += shx(q, 4);
            s += shx(s, 2); q += shx(q, 2);
            s += shx(s, 1); q += shx(q, 1);
            if (lane == 0) {
                const float mean = s * (1.0f / D_MODEL);
                const float var  = q * (1.0f / D_MODEL) - mean * mean;
                stats_s[w] = make_float2(mean, rsqrtf(var + 1e-5f));
            }
        }
        __syncthreads();                                    // b2

        // -- normalize, stage xn --
#pragma unroll
        for (int r = 0; r < RB; r++) {
            const float2 st = stats_s[r];
#pragma unroll
            for (int j = 0; j < 3; j++)
                xn_s[r * D_MODEL + t + 256 * j] = (xc[r][j] - st.x) * st.y * gj[j] + bj[j];
        }
        __syncthreads();                                    // b3

        // -- down-proj: warp (g, c); 8 values, 9-SHFL convergent butterfly --
#pragma unroll
        for (int r = 0; r < RB; r++) {
            u64 a0 = 0ull, a1 = 0ull, a2 = 0ull, a3 = 0ull;
            const float* xr = xn_s + r * D_MODEL + 192 * g + lane;
#pragma unroll
            for (int i = 0; i < 6; i++) {
                const float xs = xr[32 * i];
                const u64 xx = pk2(xs, xs);
                a0 = ffma2(xx, wd2[i][0], a0);
                a1 = ffma2(xx, wd2[i][1], a1);
                a2 = ffma2(xx, wd2[i][2], a2);
                a3 = ffma2(xx, wd2[i][3], a3);
            }
            float v0, v1, v2, v3, v4, v5, v6, v7;
            upk2(a0, v0, v1); upk2(a1, v2, v3); upk2(a2, v4, v5); upk2(a3, v6, v7);
            // stage 16: 8 -> 4 live values (4 SHFL)
            const float w0 = bfly(v0, v4, hi16, 16);
            const float w1 = bfly(v1, v5, hi16, 16);
            const float w2 = bfly(v2, v6, hi16, 16);
            const float w3 = bfly(v3, v7, hi16, 16);
            // stage 8: 4 -> 2 (2 SHFL)
            const float u0 = bfly(w0, w2, hi8, 8);
            const float u1 = bfly(w1, w3, hi8, 8);
            // stage 4: 2 -> 1 (1 SHFL)
            float z = bfly(u0, u1, hi4, 4);
            // stages 2, 1: finish 32-lane sums (2 SHFL)
            z += shx(z, 2);
            z += shx(z, 1);
            // lane 4j holds the full sum for value j  (k = 8c + j)
            if ((lane & 3) == 0)
                dpart[(r * 16 + 8 * c + (lane >> 2)) * 4 + g] = z;
        }
        __syncthreads();                                    // b4

        // -- combine d-groups + bias + relu: warp w handles row w --
        if (lane < 16) {
            const float4 p4 = reinterpret_cast<const float4*>(dpart)[w * 16 + lane];
            const float sum = (p4.x + p4.y) + (p4.z + p4.w);
            down_f[w * 16 + lane] = fmaxf(sum + bd_s[lane], 0.0f);
        }
        __syncthreads();                                    // b5

        // -- up-proj + scale + residual + next-batch prefetch --
#pragma unroll
        for (int r = 0; r < RB; r++) {
            const float4 d0 = reinterpret_cast<const float4*>(down_f)[r * 4 + 0];
            const float4 d1 = reinterpret_cast<const float4*>(down_f)[r * 4 + 1];
            const float4 d2 = reinterpret_cast<const float4*>(down_f)[r * 4 + 2];
            const float4 d3 = reinterpret_cast<const float4*>(down_f)[r * 4 + 3];
            u64 dn[8];
            dn[0] = pk2(d0.x, d0.y); dn[1] = pk2(d0.z, d0.w);
            dn[2] = pk2(d1.x, d1.y); dn[3] = pk2(d1.z, d1.w);
            dn[4] = pk2(d2.x, d2.y); dn[5] = pk2(d2.z, d2.w);
            dn[6] = pk2(d3.x, d3.y); dn[7] = pk2(d3.z, d3.w);
#pragma unroll
            for (int j = 0; j < 3; j++) {
                u64 u0 = 0ull, u1 = 0ull;
#pragma unroll
                for (int p = 0; p < 8; p += 2) {
                    u0 = ffma2(dn[p],     wu2[j][p],     u0);
                    u1 = ffma2(dn[p + 1], wu2[j][p + 1], u1);
                }
                float f0, f1, f2, f3;
                upk2(u0, f0, f1); upk2(u1, f2, f3);
                const float up = (f0 + f1) + (f2 + f3);
                out[(rbase + r) * D_MODEL + t + 256 * j] = fmaf(0.1f, up + buj[j], xc[r][j]);
            }
            if (nb < NBATCH) {
#pragma unroll
                for (int j = 0; j < 3; j++)
                    xc[r][j] = x[(nb * RB + r) * D_MODEL + t + 256 * j];
            }
        }
        // no trailing barrier: next iteration's b1/b2 order all cross-iter
        // smem hazards (writers can't reach their write sites until every
        // warp has left this phase via b1)
        b = nb;
    }
}

extern "C" void kernel_launch(void* const* d_in, const int* in_sizes, int n_in,
                              void* d_out, int out_size)
{
    const float* x    = (const float*)d_in[0];
    const float* ln_g = (const float*)d_in[1];
    const float* ln_b = (const float*)d_in[2];
    const float* wd   = (const float*)d_in[3];
    const float* bd   = (const float*)d_in[4];
    const float* wu   = (const float*)d_in[5];
    const float* bu   = (const float*)d_in[6];
    float* out = (float*)d_out;

    adapter_fused_kernel<<<GRID, NTHREADS>>>(x, ln_g, ln_b, wd, bd, wu, bu, out);
}